// round 1
// baseline (speedup 1.0000x reference)
#include <cuda_runtime.h>

#define C_CHUNKS 16
#define NCW      2048
#define SUB      64
#define DIM      1024
#define TM       128
#define TN       128

// scratch: per-codeword squared norms (16*2048 floats = 128KB)
__device__ float g_cbsq[C_CHUNKS * NCW];

// ---------------------------------------------------------------------------
// Kernel 0: codeword squared norms. One warp per codeword, coalesced float2.
// ---------------------------------------------------------------------------
__global__ void cbsq_kernel(const float* __restrict__ cb) {
    int w = (blockIdx.x * blockDim.x + threadIdx.x) >> 5;
    int lane = threadIdx.x & 31;
    if (w >= C_CHUNKS * NCW) return;
    const float2* p = reinterpret_cast<const float2*>(cb + (size_t)w * SUB);
    float2 v = p[lane];
    float s = v.x * v.x + v.y * v.y;
    #pragma unroll
    for (int o = 16; o > 0; o >>= 1) s += __shfl_xor_sync(0xffffffffu, s, o);
    if (lane == 0) g_cbsq[w] = s;
}

// ---------------------------------------------------------------------------
// Kernel 1: fused dots-GEMM + argmin + gather.
// Block = (128 tokens) x (one chunk). Loops over all 2048 codewords in tiles
// of 128 staged in SMEM. x tile loaded ONCE and reused for all 16 N-tiles.
// Each thread computes an 8x8 accumulator (classic SGEMM register blocking),
// maintains a running (min d2, argmin) for its 8 token rows, then a cross-
// thread SMEM reduction picks the block-wide argmin per token (first-index
// tie-break, matching jnp.argmin). Epilogue gathers the winning codeword
// straight to d_out.
// ---------------------------------------------------------------------------
__global__ __launch_bounds__(256, 2)
void vq_kernel(const float* __restrict__ x, const float* __restrict__ cb,
               float* __restrict__ out) {
    extern __shared__ float sm[];
    float* sA   = sm;                      // [SUB][TM]  x tile, k-major
    float* sB   = sm + SUB * TM;           // [SUB][TN]  codeword tile, k-major, permuted cols
    float* sXsq = sm + 2 * SUB * TM;       // [TM]
    int*   sIdx = reinterpret_cast<int*>(sm + 2 * SUB * TM + TM);  // [TM]

    const int tid   = threadIdx.x;
    const int chunk = blockIdx.y;
    const int t0    = blockIdx.x * TM;

    const float* cbc = cb + (size_t)chunk * NCW * SUB;
    const float* cqc = g_cbsq + chunk * NCW;

    // ---- load x tile transposed into sA, compute per-token |x|^2 ----
    {
        const int r = tid >> 1, h = tid & 1;
        const float4* xp = reinterpret_cast<const float4*>(
            x + (size_t)(t0 + r) * DIM + chunk * SUB + h * 32);
        float ssq = 0.f;
        #pragma unroll
        for (int q = 0; q < 8; q++) {
            float4 v = xp[q];
            int k = h * 32 + q * 4;
            sA[(k + 0) * TM + r] = v.x;
            sA[(k + 1) * TM + r] = v.y;
            sA[(k + 2) * TM + r] = v.z;
            sA[(k + 3) * TM + r] = v.w;
            ssq += v.x * v.x;
            ssq += v.y * v.y;
            ssq += v.z * v.z;
            ssq += v.w * v.w;
        }
        ssq += __shfl_xor_sync(0xffffffffu, ssq, 1);
        if (h == 0) sXsq[r] = ssq;
    }
    __syncthreads();

    const int ty = tid >> 4, tx = tid & 15;

    // hoist the 8 xsq values this thread needs
    float xq[8];
    #pragma unroll
    for (int i = 0; i < 8; i++) xq[i] = sXsq[ty * 8 + i];

    float minv[8];
    int   mini[8];
    #pragma unroll
    for (int i = 0; i < 8; i++) { minv[i] = 3.4028235e38f; mini[i] = 0; }

    for (int n0 = 0; n0 < NCW; n0 += TN) {
        __syncthreads();   // protect sB reuse from previous iteration's readers
        {
            // Store codeword r's k-values at permuted column m so that the
            // inner-loop float4 reads (tx*4 and 64+tx*4) are conflict-free.
            const int r = tid >> 1, h = tid & 1;
            const int m = ((r & 4) << 4) | ((r >> 3) << 2) | (r & 3);
            const float4* cp = reinterpret_cast<const float4*>(
                cbc + (size_t)(n0 + r) * SUB + h * 32);
            #pragma unroll
            for (int q = 0; q < 8; q++) {
                float4 v = cp[q];
                int k = h * 32 + q * 4;
                sB[(k + 0) * TN + m] = v.x;
                sB[(k + 1) * TN + m] = v.y;
                sB[(k + 2) * TN + m] = v.z;
                sB[(k + 3) * TN + m] = v.w;
            }
        }
        __syncthreads();

        float acc[8][8];
        #pragma unroll
        for (int i = 0; i < 8; i++)
            #pragma unroll
            for (int j = 0; j < 8; j++) acc[i][j] = 0.f;

        #pragma unroll 4
        for (int k = 0; k < SUB; k++) {
            float4 a0 = *reinterpret_cast<const float4*>(&sA[k * TM + ty * 8]);
            float4 a1 = *reinterpret_cast<const float4*>(&sA[k * TM + ty * 8 + 4]);
            float4 b0 = *reinterpret_cast<const float4*>(&sB[k * TN + tx * 4]);
            float4 b1 = *reinterpret_cast<const float4*>(&sB[k * TN + 64 + tx * 4]);
            float ra[8] = {a0.x, a0.y, a0.z, a0.w, a1.x, a1.y, a1.z, a1.w};
            float rb[8] = {b0.x, b0.y, b0.z, b0.w, b1.x, b1.y, b1.z, b1.w};
            #pragma unroll
            for (int i = 0; i < 8; i++)
                #pragma unroll
                for (int j = 0; j < 8; j++)
                    acc[i][j] = fmaf(ra[i], rb[j], acc[i][j]);
        }

        // d2 = xsq - 2*dot + cbsq ; running argmin (n ascending, strict <)
        #pragma unroll
        for (int j = 0; j < 8; j++) {
            int n = n0 + tx * 8 + j;
            float cq = __ldg(&cqc[n]);
            #pragma unroll
            for (int i = 0; i < 8; i++) {
                float d2 = fmaf(-2.f, acc[i][j], xq[i]) + cq;
                if (d2 < minv[i]) { minv[i] = d2; mini[i] = n; }
            }
        }
    }

    // ---- cross-thread argmin reduction (overlay on sB, padded stride 17) ----
    __syncthreads();
    float* redv = sB;
    int*   redi = reinterpret_cast<int*>(sB + TM * 17);
    #pragma unroll
    for (int i = 0; i < 8; i++) {
        int row = ty * 8 + i;
        redv[row * 17 + tx] = minv[i];
        redi[row * 17 + tx] = mini[i];
    }
    __syncthreads();
    if (tid < TM) {
        float bv = redv[tid * 17];
        int   bi = redi[tid * 17];
        #pragma unroll
        for (int t = 1; t < 16; t++) {
            float v  = redv[tid * 17 + t];
            int   ii = redi[tid * 17 + t];
            if (v < bv || (v == bv && ii < bi)) { bv = v; bi = ii; }
        }
        sIdx[tid] = bi;
    }
    __syncthreads();

    // ---- gather winning codewords straight to output (K == 1) ----
    {
        const int r = tid >> 1, h = tid & 1;
        const int idx = sIdx[r];
        const float4* src = reinterpret_cast<const float4*>(
            cbc + (size_t)idx * SUB + h * 32);
        float4* dst = reinterpret_cast<float4*>(
            out + (size_t)(t0 + r) * DIM + chunk * SUB + h * 32);
        #pragma unroll
        for (int q = 0; q < 8; q++) dst[q] = src[q];
    }
}

extern "C" void kernel_launch(void* const* d_in, const int* in_sizes, int n_in,
                              void* d_out, int out_size) {
    const float* x  = (const float*)d_in[0];   // (4, 2048, 1024) fp32
    const float* cb = (const float*)d_in[1];   // (16, 2048, 64) fp32
    float* out = (float*)d_out;

    const int tokens = in_sizes[0] / DIM;      // 8192

    // Kernel 0: codeword norms (one warp per codeword)
    int n_warps = C_CHUNKS * NCW;
    cbsq_kernel<<<(n_warps * 32 + 255) / 256, 256>>>(cb);

    // Kernel 1: fused search + gather
    size_t smem = (size_t)(2 * SUB * TM + TM) * sizeof(float) + TM * sizeof(int);
    cudaFuncSetAttribute(vq_kernel,
                         cudaFuncAttributeMaxDynamicSharedMemorySize, (int)smem);
    dim3 grid(tokens / TM, C_CHUNKS);
    vq_kernel<<<grid, 256, smem>>>(x, cb, out);
}